// round 11
// baseline (speedup 1.0000x reference)
#include <cuda_runtime.h>
#include <cstdint>

// MarginalCalibrationPlot: per-(class, bin) calibration stats.
// probas: [N, C] float32 (row-major), labels: [N] int32 or int64.
// Output: [confs(C*B) | accs(C*B) | n_samples(C*B)] float32, seg = c*B + b.

#define CCOUNT 100
#define NBINS  15
#define NSEG   (CCOUNT * NBINS)
#define TPB    128
#define GRID_ACC 608   // ~4 blocks/SM on 152-SM GB300

__device__ float g_cnt[NSEG];
__device__ float g_sum[NSEG];
__device__ float g_sua[NSEG];
__device__ int   g_is64;

// Bin edges matching jnp.linspace(0,1,16,float32):
// edge[k] = fl(k * fl(1/15)) for k<15, edge[15] = 1.0 (endpoint override).
__device__ __forceinline__ float edgef(int k) {
    return (k >= NBINS) ? 1.0f : (float)k * (1.0f / 15.0f);
}

// -------- init: zero accumulators + detect labels dtype (int64 vs int32) ----
__global__ void init_kernel(const void* __restrict__ labels, int N) {
    int i = blockIdx.x * blockDim.x + threadIdx.x;
    if (i < NSEG) { g_cnt[i] = 0.0f; g_sum[i] = 0.0f; g_sua[i] = 0.0f; }
    if (blockIdx.x == 0) {
        __shared__ int s_ok;
        if (threadIdx.x == 0) s_ok = 1;
        __syncthreads();
        // If the buffer is int32, reading it as int64 pairs two labels:
        // value = lo + hi*2^32 with hi in [0,99]; any hi>0 makes v >= 2^32.
        // P(128 consecutive hi==0) = 1e-256, so this is a safe discriminator.
        int nchk = (N >= 256) ? 128 : (N / 2);
        if ((int)threadIdx.x < nchk) {
            const long long* l64 = (const long long*)labels;
            long long v = l64[threadIdx.x];
            if (v < 0 || v >= CCOUNT) atomicAnd(&s_ok, 0);
        }
        __syncthreads();
        if (threadIdx.x == 0) g_is64 = s_ok;
    }
}

// -------- main accumulation ------------------------------------------------
__global__ void __launch_bounds__(TPB) accum_kernel(
    const float* __restrict__ probas,
    const void*  __restrict__ labels,
    int N)
{
    // Per-thread-private accumulators in shared memory (no atomics in hot loop).
    // Layout [bin][tid]: word bank = tid mod 32 -> conflict-free.
    __shared__ float2 s_cs[NBINS][TPB];   // {count, sum_p}
    __shared__ float  s_a [NBINS][TPB];   // sum_correct

    const int t = threadIdx.x;
    #pragma unroll
    for (int b = 0; b < NBINS; ++b) {
        s_cs[b][t] = make_float2(0.0f, 0.0f);
        s_a [b][t] = 0.0f;
    }
    __syncthreads();

    const int sh = g_is64;                      // 1 if int64 labels, else 0
    const int* __restrict__ l32 = (const int*)labels;  // low word carries the label

    const int rows = (N + gridDim.x - 1) / gridDim.x;
    const int r0 = blockIdx.x * rows;
    const int r1 = min(N, r0 + rows);

    if (t < CCOUNT && r0 < r1) {
        const float* p_ptr = probas + (size_t)r0 * CCOUNT + t;
        int r = r0;

        #define CAL_BODY(P, LB) do {                                          \
            float p_ = (P);                                                   \
            int k_ = (int)(p_ * 15.0f);                                       \
            k_ = max(0, min(k_, NBINS));                                      \
            if (k_ < NBINS && edgef(k_ + 1) <= p_) ++k_;                      \
            if (k_ > 0 && edgef(k_) > p_) --k_;                               \
            if (p_ > 0.01f && k_ < NBINS && p_ > edgef(k_)) {                 \
                float2 v_ = s_cs[k_][t];                                      \
                v_.x += 1.0f; v_.y += p_;                                     \
                s_cs[k_][t] = v_;                                             \
                if ((LB) == t) s_a[k_][t] += 1.0f;                            \
            } } while (0)

        // 8-row unroll for memory-level parallelism.
        for (; r + 8 <= r1; r += 8) {
            float p[8]; int lb[8];
            #pragma unroll
            for (int u = 0; u < 8; ++u) p[u] = p_ptr[u * CCOUNT];
            #pragma unroll
            for (int u = 0; u < 8; ++u) lb[u] = l32[(r + u) << sh];
            #pragma unroll
            for (int u = 0; u < 8; ++u) CAL_BODY(p[u], lb[u]);
            p_ptr += 8 * CCOUNT;
        }
        for (; r < r1; ++r) {
            float p = *p_ptr;
            int lb = l32[r << sh];
            CAL_BODY(p, lb);
            p_ptr += CCOUNT;
        }
        #undef CAL_BODY
    }
    __syncthreads();

    // Column t's accumulators ARE this block's partials for class t.
    if (t < CCOUNT) {
        #pragma unroll
        for (int b = 0; b < NBINS; ++b) {
            const int seg = t * NBINS + b;
            float2 v = s_cs[b][t];
            if (v.x != 0.0f) {
                atomicAdd(&g_cnt[seg], v.x);
                atomicAdd(&g_sum[seg], v.y);
            }
            float a = s_a[b][t];
            if (a != 0.0f) atomicAdd(&g_sua[seg], a);
        }
    }
}

// -------- finalize: confs / accs / n_samples with NaN for empty bins --------
__global__ void finalize_kernel(float* __restrict__ out) {
    int i = blockIdx.x * blockDim.x + threadIdx.x;
    if (i < NSEG) {
        float c = g_cnt[i];
        float conf, acc;
        if (c > 0.0f) {
            conf = g_sum[i] / c;
            acc  = g_sua[i] / c;
        } else {
            conf = __int_as_float(0x7fc00000);
            acc  = conf;
        }
        out[i]            = conf;
        out[NSEG + i]     = acc;
        out[2 * NSEG + i] = c;
    }
}

extern "C" void kernel_launch(void* const* d_in, const int* in_sizes, int n_in,
                              void* d_out, int out_size) {
    const float* probas = (const float*)d_in[0];
    const void*  labels = d_in[1];
    const int N = in_sizes[0] / CCOUNT;

    init_kernel<<<(NSEG + 255) / 256, 256>>>(labels, N);
    accum_kernel<<<GRID_ACC, TPB>>>(probas, labels, N);
    finalize_kernel<<<(NSEG + 255) / 256, 256>>>((float*)d_out);
}

// round 12
// speedup vs baseline: 2.0555x; 2.0555x over previous
#include <cuda_runtime.h>
#include <cstdint>

// MarginalCalibrationPlot: per-(class, bin) calibration stats.
// probas: [N, C] float32 row-major, labels: [N] int32 or int64.
// Output: [confs(C*B) | accs(C*B) | n_samples(C*B)] float32, seg = c*B + b.

#define CCOUNT 100
#define NBINS  15
#define NSEG   (CCOUNT * NBINS)
#define TPB    512
#define ACTIVE 500          // active threads per block; multiple of CCOUNT
#define GRID_ACC 304        // 2 blocks/SM on 152-SM GB300
#define INV15  (1.0f / 15.0f)

__device__ float g_cnt[NSEG];
__device__ float g_sum[NSEG];
__device__ float g_sua[NSEG];
__device__ int   g_is64;

// -------- init: zero accumulators + detect labels dtype (int64 vs int32) ----
__global__ void init_kernel(const void* __restrict__ labels, int N) {
    int i = blockIdx.x * blockDim.x + threadIdx.x;
    if (i < NSEG) { g_cnt[i] = 0.0f; g_sum[i] = 0.0f; g_sua[i] = 0.0f; }
    if (blockIdx.x == 0) {
        __shared__ int s_ok;
        if (threadIdx.x == 0) s_ok = 1;
        __syncthreads();
        // int32 buffer read as int64 pairs two labels: any hi-word > 0 makes
        // v >= 2^32. P(128 consecutive hi==0) ~ 1e-256 => safe discriminator.
        int nchk = (N >= 256) ? 128 : (N / 2);
        if ((int)threadIdx.x < nchk) {
            const long long* l64 = (const long long*)labels;
            long long v = l64[threadIdx.x];
            if (v < 0 || v >= CCOUNT) atomicAnd(&s_ok, 0);
        }
        __syncthreads();
        if (threadIdx.x == 0) g_is64 = s_ok;
    }
}

// -------- main accumulation: branchless, flat-index, packed float2 ----------
__global__ void __launch_bounds__(TPB, 2) accum_kernel(
    const float* __restrict__ probas,
    const void*  __restrict__ labels,
    int N)
{
    // Dynamic shared: [NBINS][TPB] float2 {count*4096 + acc, sum_p}.
    // Per-thread-private slots => zero atomics, zero branches in hot loop.
    extern __shared__ float2 s2[];

    const int t = threadIdx.x;
    #pragma unroll
    for (int b = 0; b < NBINS; ++b) s2[b * TPB + t] = make_float2(0.0f, 0.0f);
    __syncthreads();

    const int sh = g_is64;                              // 1 if int64, else 0
    const int* __restrict__ l32 = (const int*)labels;   // low word = label

    const long long E     = (long long)N * CCOUNT;
    const long long units = E / ACTIVE;                 // full 500-elem groups
    const int       rem   = (int)(E - units * ACTIVE);
    const long long perBlk = (units + gridDim.x - 1) / gridDim.x;
    const long long u0 = (long long)blockIdx.x * perBlk;
    long long u1 = u0 + perBlk; if (u1 > units) u1 = units;

    const int c  = t % CCOUNT;   // fixed column for this thread
    const int rq = t / CCOUNT;   // fixed row offset within a 5-row group

    // Branchless per-element body. Bin edges replicate
    // jnp.linspace(0,1,16,f32): edge[k] = fl(k*fl(1/15)), edge[15]=1.0.
    // floor(p*15) is within +-1 of the searchsorted bin; two predicate
    // corrections fix it. fminf(...,1) reproduces the endpoint override.
    #define BODY(P, LB) do {                                                  \
        float p_  = (P);                                                      \
        float kf_ = floorf(p_ * 15.0f);                                       \
        float eh_ = fminf(fmaf(kf_, INV15, INV15), 1.0f);                     \
        kf_ += (eh_ <= p_) ? 1.0f : 0.0f;                                     \
        float el_ = fminf(kf_ * INV15, 1.0f);                                 \
        kf_ -= (el_ > p_) ? 1.0f : 0.0f;                                      \
        float lf_ = fminf(kf_ * INV15, 1.0f);                                 \
        float w_  = ((p_ > 0.01f) && (p_ > lf_)) ? 1.0f : 0.0f;               \
        float wa_ = ((LB) == c) ? w_ : 0.0f;                                  \
        int bi_   = (int)fminf(fmaxf(kf_, 0.0f), 14.0f);                      \
        float2 v_ = s2[bi_ * TPB + t];                                        \
        v_.x = fmaf(w_, 4096.0f, v_.x) + wa_;                                 \
        v_.y = fmaf(w_, p_, v_.y);                                            \
        s2[bi_ * TPB + t] = v_;                                               \
    } while (0)

    if (t < ACTIVE && u0 < u1) {
        const float* pp = probas + u0 * ACTIVE + t;
        long long row = u0 * 5 + rq;       // row = e/100, e = u*500 + t
        const long long nu = u1 - u0;
        long long i = 0;
        for (; i + 4 <= nu; i += 4) {
            float p0 = pp[0 * ACTIVE], p1 = pp[1 * ACTIVE];
            float p2 = pp[2 * ACTIVE], p3 = pp[3 * ACTIVE];
            int lb0 = l32[(row      ) << sh];
            int lb1 = l32[(row +  5 ) << sh];
            int lb2 = l32[(row + 10 ) << sh];
            int lb3 = l32[(row + 15 ) << sh];
            BODY(p0, lb0); BODY(p1, lb1); BODY(p2, lb2); BODY(p3, lb3);
            pp += 4 * ACTIVE; row += 20;
        }
        for (; i < nu; ++i) {
            float p = pp[0];
            int lb = l32[row << sh];
            BODY(p, lb);
            pp += ACTIVE; row += 5;
        }
    }
    // Tail (E not a multiple of ACTIVE): block 0, threads t < rem.
    // units*500 % 100 == 0, so col = t%100 and slot t stay consistent.
    if (blockIdx.x == 0 && t < rem) {
        float p = probas[units * ACTIVE + t];
        int lb = l32[(units * 5 + rq) << sh];
        BODY(p, lb);
    }
    #undef BODY
    __syncthreads();

    // Epilogue: fold 5 sub-slots per (bin,col), decode packed, global atomics.
    for (int idx = t; idx < NSEG; idx += TPB) {
        const int b   = idx % NBINS;
        const int col = idx / NBINS;
        float px = 0.0f, py = 0.0f;
        #pragma unroll
        for (int j = 0; j < 5; ++j) {
            float2 v = s2[b * TPB + col + j * CCOUNT];
            px += v.x; py += v.y;
        }
        // px = cnt*4096 + acc, both exact integers (cnt <= ~1100 per block)
        float cnt = floorf(px * (1.0f / 4096.0f));
        float acc = px - cnt * 4096.0f;
        const int seg = col * NBINS + b;
        if (cnt != 0.0f) {
            atomicAdd(&g_cnt[seg], cnt);
            atomicAdd(&g_sum[seg], py);
            if (acc != 0.0f) atomicAdd(&g_sua[seg], acc);
        }
    }
}

// -------- finalize: confs / accs / n_samples with NaN for empty bins --------
__global__ void finalize_kernel(float* __restrict__ out) {
    int i = blockIdx.x * blockDim.x + threadIdx.x;
    if (i < NSEG) {
        float cv = g_cnt[i];
        float conf, acc;
        if (cv > 0.0f) {
            conf = g_sum[i] / cv;
            acc  = g_sua[i] / cv;
        } else {
            conf = __int_as_float(0x7fc00000);
            acc  = conf;
        }
        out[i]            = conf;
        out[NSEG + i]     = acc;
        out[2 * NSEG + i] = cv;
    }
}

extern "C" void kernel_launch(void* const* d_in, const int* in_sizes, int n_in,
                              void* d_out, int out_size) {
    const float* probas = (const float*)d_in[0];
    const void*  labels = d_in[1];
    const int N = in_sizes[0] / CCOUNT;

    const size_t smem = (size_t)NBINS * TPB * sizeof(float2);  // 61440 B
    cudaFuncSetAttribute(accum_kernel,
                         cudaFuncAttributeMaxDynamicSharedMemorySize, (int)smem);

    init_kernel<<<(NSEG + 255) / 256, 256>>>(labels, N);
    accum_kernel<<<GRID_ACC, TPB, smem>>>(probas, labels, N);
    finalize_kernel<<<(NSEG + 255) / 256, 256>>>((float*)d_out);
}